// round 9
// baseline (speedup 1.0000x reference)
#include <cuda_runtime.h>
#include <cuda_fp16.h>
#include <cstdint>
#include <cstddef>

// ---------------- problem dims ----------------
constexpr int DIMX   = 2048;
constexpr int DINNER = 2048;
constexpr int BATCH  = 4;
constexpr int TLEN   = 4096;
constexpr int MROWS  = BATCH * TLEN;     // 16384
constexpr int CHUNK  = 128;              // scan chunk length
constexpr int NCHUNK = TLEN / CHUNK;     // 32

// ---------------- GEMM tiling (shared geometry: 128B rows, 16B chunks) ------
constexpr int BM = 128, BN = 128;
constexpr int TILE_B = 128 * 128;        // 16384 bytes per smem tile (128 rows x 128B)

// GEMM1 (int8): K = 2048 bytes, BK = 128 bytes/stage -> 16 stages, 4 tiles/stage
constexpr int G1_STAGE_B = 4 * TILE_B;          // Ah,Al,Bh,Bl = 65536
constexpr int G1_SMEM    = 2 * G1_STAGE_B;      // 131072
// GEMM2 (fp16): K = 2048 halves, BK = 64 halves/stage -> 32 stages, 3 tiles/stage
constexpr int G2_STAGE_B = 3 * TILE_B;          // A,Bh,Bl = 49152
constexpr int G2_SMEM    = 2 * G2_STAGE_B;      // 98304

// quantization scales
constexpr float QX   = 4096.0f;                  // x: |x| <= ~7.96
constexpr float QW   = 819200.0f;                // W_in: |w| <= 0.0383 -> q <= 31385
constexpr float INV1 = 1.0f / (QX * QW);

// ---------------- device scratch (no allocations allowed) ----------------
__device__ __align__(256) int8_t g_xah[(size_t)MROWS * DIMX];
__device__ __align__(256) int8_t g_xal[(size_t)MROWS * DIMX];
__device__ __align__(256) int8_t g_wih[(size_t)DINNER * DIMX];
__device__ __align__(256) int8_t g_wil[(size_t)DINNER * DIMX];
__device__ __align__(256) __half g_woh[(size_t)DIMX * DINNER];
__device__ __align__(256) __half g_wol[(size_t)DIMX * DINNER];
__device__ __align__(256) float  g_xp[(size_t)MROWS * DINNER];
__device__ __align__(256) __half g_ch[(size_t)MROWS * DINNER];
__device__ __align__(256) float  g_carry[(size_t)BATCH * NCHUNK * DINNER];
__device__ __align__(256) float  g_hin[(size_t)BATCH * NCHUNK * DINNER];

// ---------------- helpers ----------------
__device__ __forceinline__ float sigmoidf_(float x) { return 1.f / (1.f + __expf(-x)); }
__device__ __forceinline__ float siluf(float x)     { return x * sigmoidf_(x); }

__device__ __forceinline__ void cp16(uint32_t saddr, const void* gaddr) {
    asm volatile("cp.async.cg.shared.global [%0], [%1], 16;\n" :: "r"(saddr), "l"(gaddr));
}
__device__ __forceinline__ void ldm4(uint32_t (&d)[4], uint32_t saddr) {
    asm volatile("ldmatrix.sync.aligned.m8n8.x4.shared.b16 {%0,%1,%2,%3}, [%4];\n"
                 : "=r"(d[0]), "=r"(d[1]), "=r"(d[2]), "=r"(d[3]) : "r"(saddr));
}
__device__ __forceinline__ void mma_s8(int (&c)[4], const uint32_t (&a)[4], const uint32_t* b) {
    asm volatile("mma.sync.aligned.m16n8k32.row.col.s32.s8.s8.s32 "
                 "{%0,%1,%2,%3},{%4,%5,%6,%7},{%8,%9},{%0,%1,%2,%3};\n"
                 : "+r"(c[0]), "+r"(c[1]), "+r"(c[2]), "+r"(c[3])
                 : "r"(a[0]), "r"(a[1]), "r"(a[2]), "r"(a[3]), "r"(b[0]), "r"(b[1]));
}
__device__ __forceinline__ void mma_f16(float (&c)[4], const uint32_t (&a)[4], const uint32_t* b) {
    asm volatile("mma.sync.aligned.m16n8k16.row.col.f32.f16.f16.f32 "
                 "{%0,%1,%2,%3},{%4,%5,%6,%7},{%8,%9},{%0,%1,%2,%3};\n"
                 : "+f"(c[0]), "+f"(c[1]), "+f"(c[2]), "+f"(c[3])
                 : "r"(a[0]), "r"(a[1]), "r"(a[2]), "r"(a[3]), "r"(b[0]), "r"(b[1]));
}

// ---------------- quantize fp32 -> int16 fixed point, split into s8 hi/lo ----
__global__ void quant_s8_kernel(const float4* __restrict__ src,
                                uchar4* __restrict__ hi, uchar4* __restrict__ lo,
                                float scale, int n4)
{
    int i = blockIdx.x * blockDim.x + threadIdx.x;
    int stride = gridDim.x * blockDim.x;
    for (; i < n4; i += stride) {
        float4 v = src[i];
        int q[4];
        q[0] = __float2int_rn(v.x * scale);
        q[1] = __float2int_rn(v.y * scale);
        q[2] = __float2int_rn(v.z * scale);
        q[3] = __float2int_rn(v.w * scale);
        uchar4 H, L;
        unsigned char hb[4], lb[4];
#pragma unroll
        for (int j = 0; j < 4; j++) {
            int qq = q[j];
            qq = qq >  32639 ?  32639 : qq;
            qq = qq < -32639 ? -32639 : qq;
            int al = (int)(signed char)(qq & 0xFF);   // low byte as signed
            int ah = (qq - al) >> 8;                  // exact: qq = 256*ah + al
            lb[j] = (unsigned char)(al & 0xFF);
            hb[j] = (unsigned char)(ah & 0xFF);
        }
        H.x = hb[0]; H.y = hb[1]; H.z = hb[2]; H.w = hb[3];
        L.x = lb[0]; L.y = lb[1]; L.z = lb[2]; L.w = lb[3];
        hi[i] = H; lo[i] = L;
    }
}

// ---------------- fp32 -> fp16 hi/lo split (for W_out) ----------------
__global__ void split_f16_kernel(const float4* __restrict__ src,
                                 uint2* __restrict__ hi, uint2* __restrict__ lo, int n4)
{
    int i = blockIdx.x * blockDim.x + threadIdx.x;
    int stride = gridDim.x * blockDim.x;
    for (; i < n4; i += stride) {
        float4 v = src[i];
        __half hx = __float2half_rn(v.x), hy = __float2half_rn(v.y);
        __half hz = __float2half_rn(v.z), hw = __float2half_rn(v.w);
        __half lx = __float2half_rn(v.x - __half2float(hx));
        __half ly = __float2half_rn(v.y - __half2float(hy));
        __half lz = __float2half_rn(v.z - __half2float(hz));
        __half lw = __float2half_rn(v.w - __half2float(hw));
        uint2 H, L;
        H.x = ((uint32_t)__half_as_ushort(hy) << 16) | __half_as_ushort(hx);
        H.y = ((uint32_t)__half_as_ushort(hw) << 16) | __half_as_ushort(hz);
        L.x = ((uint32_t)__half_as_ushort(ly) << 16) | __half_as_ushort(lx);
        L.y = ((uint32_t)__half_as_ushort(lw) << 16) | __half_as_ushort(lz);
        hi[i] = H; lo[i] = L;
    }
}

// ---------------- GEMM1: int8 dual-word, C = silu(A*B^T * INV1) -------------
// A[M,K] s8 (hi,lo planar), B[N,K] s8 (hi,lo planar), K in bytes.
// acc_hh += Ah*Bh ; acc_mid += Ah*Bl + Al*Bh ; C = (65536*hh + 256*mid)*INV1.
__global__ void __launch_bounds__(256, 1)
gemm_s8_silu(const int8_t* __restrict__ Ah, const int8_t* __restrict__ Al,
             const int8_t* __restrict__ Bh, const int8_t* __restrict__ Bl,
             float* __restrict__ C, int M, int N, int K)
{
    extern __shared__ char smem[];
    const int tid  = threadIdx.x;
    const int lane = tid & 31;
    const int wid  = tid >> 5;
    const int wm   = (wid >> 2) * 64;   // 2 warps in M
    const int wn   = (wid & 3) * 32;    // 4 warps in N
    const int bm   = blockIdx.y * BM;
    const int bn   = blockIdx.x * BN;
    const uint32_t sbase = (uint32_t)__cvta_generic_to_shared(smem);

    int hh[4][4][4], mid[4][4][4];
#pragma unroll
    for (int i = 0; i < 4; i++)
#pragma unroll
        for (int j = 0; j < 4; j++)
#pragma unroll
            for (int q = 0; q < 4; q++) { hh[i][j][q] = 0; mid[i][j][q] = 0; }

    const int8_t* gA_h = Ah + (size_t)bm * K;
    const int8_t* gA_l = Al + (size_t)bm * K;
    const int8_t* gB_h = Bh + (size_t)bn * K;
    const int8_t* gB_l = Bl + (size_t)bn * K;

    const int c_ld  = tid & 7;    // 16B chunk within 128B row
    const int r0_ld = tid >> 3;   // row 0..31 (+32 per iter)

    // prologue: stage 0
    {
        uint32_t st = sbase;
#pragma unroll
        for (int it = 0; it < 4; it++) {
            int r = r0_ld + it * 32;
            uint32_t soff = (uint32_t)(r * 128 + ((c_ld ^ (r & 7)) << 4));
            size_t goff = (size_t)r * K + c_ld * 16;
            cp16(st + soff,              gA_h + goff);
            cp16(st + TILE_B + soff,     gA_l + goff);
            cp16(st + 2 * TILE_B + soff, gB_h + goff);
            cp16(st + 3 * TILE_B + soff, gB_l + goff);
        }
        asm volatile("cp.async.commit_group;" ::: "memory");
    }

    const int NK = K / 128;   // 16 stages
#pragma unroll 1
    for (int ks = 0; ks < NK; ks++) {
        const int cur = ks & 1;
        if (ks + 1 < NK) {
            uint32_t st = sbase + (uint32_t)(cur ^ 1) * G1_STAGE_B;
            int k0 = (ks + 1) * 128;
#pragma unroll
            for (int it = 0; it < 4; it++) {
                int r = r0_ld + it * 32;
                uint32_t soff = (uint32_t)(r * 128 + ((c_ld ^ (r & 7)) << 4));
                size_t goff = (size_t)r * K + k0 + c_ld * 16;
                cp16(st + soff,              gA_h + goff);
                cp16(st + TILE_B + soff,     gA_l + goff);
                cp16(st + 2 * TILE_B + soff, gB_h + goff);
                cp16(st + 3 * TILE_B + soff, gB_l + goff);
            }
        }
        asm volatile("cp.async.commit_group;" ::: "memory");
        asm volatile("cp.async.wait_group 1;" ::: "memory");
        __syncthreads();

        uint32_t st = sbase + (uint32_t)cur * G1_STAGE_B;
        uint32_t sA[2] = { st,              st + TILE_B };
        uint32_t sB[2] = { st + 2 * TILE_B, st + 3 * TILE_B };

#pragma unroll
        for (int kk = 0; kk < 4; kk++) {          // 4 x k32 per stage
            uint32_t a[2][4][4];
            {
                int ra  = wm + (lane & 15);
                int cha = kk * 2 + (lane >> 4);
#pragma unroll
                for (int h = 0; h < 2; h++)
#pragma unroll
                    for (int mt = 0; mt < 4; mt++) {
                        int r = ra + mt * 16;
                        ldm4(a[h][mt], sA[h] + (uint32_t)(r * 128 + ((cha ^ (r & 7)) << 4)));
                    }
            }
            uint32_t b[2][4][2];
            {
                int rb  = wn + ((lane >> 4) << 3) + (lane & 7);
                int chb = kk * 2 + ((lane >> 3) & 1);
#pragma unroll
                for (int h = 0; h < 2; h++)
#pragma unroll
                    for (int p = 0; p < 2; p++) {
                        int r = rb + p * 16;
                        uint32_t t4[4];
                        ldm4(t4, sB[h] + (uint32_t)(r * 128 + ((chb ^ (r & 7)) << 4)));
                        b[h][2 * p    ][0] = t4[0]; b[h][2 * p    ][1] = t4[1];
                        b[h][2 * p + 1][0] = t4[2]; b[h][2 * p + 1][1] = t4[3];
                    }
            }
#pragma unroll
            for (int mt = 0; mt < 4; mt++)
#pragma unroll
                for (int nt = 0; nt < 4; nt++) {
                    mma_s8(hh[mt][nt],  a[0][mt], b[0][nt]);  // hi*hi
                    mma_s8(mid[mt][nt], a[0][mt], b[1][nt]);  // hi*lo
                    mma_s8(mid[mt][nt], a[1][mt], b[0][nt]);  // lo*hi
                }
        }
        __syncthreads();
    }

    // epilogue
#pragma unroll
    for (int mt = 0; mt < 4; mt++) {
        int row = bm + wm + mt * 16 + (lane >> 2);
#pragma unroll
        for (int nt = 0; nt < 4; nt++) {
            int col = bn + wn + nt * 8 + (lane & 3) * 2;
            float v[4];
#pragma unroll
            for (int q = 0; q < 4; q++) {
                v[q] = (65536.0f * (float)hh[mt][nt][q] + 256.0f * (float)mid[mt][nt][q]) * INV1;
                v[q] = siluf(v[q]);
            }
            float* p0 = C + (size_t)row * N + col;
            p0[0] = v[0]; p0[1] = v[1];
            float* p1 = C + (size_t)(row + 8) * N + col;
            p1[0] = v[2]; p1[1] = v[3];
        }
    }
}

// ---------------- GEMM2: fp16 2-product, C = A*(Bh+Bl)^T --------------------
// A[M,K] fp16 single, B[N,K] fp16 hi/lo planar. acc += A*Bh + A*Bl (fp32).
__global__ void __launch_bounds__(256, 1)
gemm_f16_2p(const __half* __restrict__ A,
            const __half* __restrict__ Bh, const __half* __restrict__ Bl,
            float* __restrict__ C, int M, int N, int K)
{
    extern __shared__ char smem[];
    const int tid  = threadIdx.x;
    const int lane = tid & 31;
    const int wid  = tid >> 5;
    const int wm   = (wid >> 2) * 64;
    const int wn   = (wid & 3) * 32;
    const int bm   = blockIdx.y * BM;
    const int bn   = blockIdx.x * BN;
    const uint32_t sbase = (uint32_t)__cvta_generic_to_shared(smem);

    float acc[4][4][4];
#pragma unroll
    for (int i = 0; i < 4; i++)
#pragma unroll
        for (int j = 0; j < 4; j++)
#pragma unroll
            for (int q = 0; q < 4; q++) acc[i][j][q] = 0.f;

    const __half* gA   = A  + (size_t)bm * K;
    const __half* gB_h = Bh + (size_t)bn * K;
    const __half* gB_l = Bl + (size_t)bn * K;

    const int c_ld  = tid & 7;
    const int r0_ld = tid >> 3;

    {
        uint32_t st = sbase;
#pragma unroll
        for (int it = 0; it < 4; it++) {
            int r = r0_ld + it * 32;
            uint32_t soff = (uint32_t)(r * 128 + ((c_ld ^ (r & 7)) << 4));
            size_t goff = (size_t)r * K + c_ld * 8;
            cp16(st + soff,              gA   + goff);
            cp16(st + TILE_B + soff,     gB_h + goff);
            cp16(st + 2 * TILE_B + soff, gB_l + goff);
        }
        asm volatile("cp.async.commit_group;" ::: "memory");
    }

    const int NK = K / 64;   // 32 stages
#pragma unroll 1
    for (int ks = 0; ks < NK; ks++) {
        const int cur = ks & 1;
        if (ks + 1 < NK) {
            uint32_t st = sbase + (uint32_t)(cur ^ 1) * G2_STAGE_B;
            int k0 = (ks + 1) * 64;
#pragma unroll
            for (int it = 0; it < 4; it++) {
                int r = r0_ld + it * 32;
                uint32_t soff = (uint32_t)(r * 128 + ((c_ld ^ (r & 7)) << 4));
                size_t goff = (size_t)r * K + k0 + c_ld * 8;
                cp16(st + soff,              gA   + goff);
                cp16(st + TILE_B + soff,     gB_h + goff);
                cp16(st + 2 * TILE_B + soff, gB_l + goff);
            }
        }
        asm volatile("cp.async.commit_group;" ::: "memory");
        asm volatile("cp.async.wait_group 1;" ::: "memory");
        __syncthreads();

        uint32_t st = sbase + (uint32_t)cur * G2_STAGE_B;
        uint32_t sA = st;
        uint32_t sB[2] = { st + TILE_B, st + 2 * TILE_B };

#pragma unroll
        for (int kk = 0; kk < 4; kk++) {
            uint32_t a[4][4];
            {
                int ra  = wm + (lane & 15);
                int cha = kk * 2 + (lane >> 4);
#pragma unroll
                for (int mt = 0; mt < 4; mt++) {
                    int r = ra + mt * 16;
                    ldm4(a[mt], sA + (uint32_t)(r * 128 + ((cha ^ (r & 7)) << 4)));
                }
            }
            uint32_t b[2][4][2];
            {
                int rb  = wn + ((lane >> 4) << 3) + (lane & 7);
                int chb = kk * 2 + ((lane >> 3) & 1);
#pragma unroll
                for (int h = 0; h < 2; h++)
#pragma unroll
                    for (int p = 0; p < 2; p++) {
                        int r = rb + p * 16;
                        uint32_t t4[4];
                        ldm4(t4, sB[h] + (uint32_t)(r * 128 + ((chb ^ (r & 7)) << 4)));
                        b[h][2 * p    ][0] = t4[0]; b[h][2 * p    ][1] = t4[1];
                        b[h][2 * p + 1][0] = t4[2]; b[h][2 * p + 1][1] = t4[3];
                    }
            }
#pragma unroll
            for (int mt = 0; mt < 4; mt++)
#pragma unroll
                for (int nt = 0; nt < 4; nt++) {
                    mma_f16(acc[mt][nt], a[mt], b[0][nt]);  // A*Bh
                    mma_f16(acc[mt][nt], a[mt], b[1][nt]);  // A*Bl
                }
        }
        __syncthreads();
    }

#pragma unroll
    for (int mt = 0; mt < 4; mt++) {
        int row = bm + wm + mt * 16 + (lane >> 2);
#pragma unroll
        for (int nt = 0; nt < 4; nt++) {
            int col = bn + wn + nt * 8 + (lane & 3) * 2;
            float* p0 = C + (size_t)row * N + col;
            p0[0] = acc[mt][nt][0]; p0[1] = acc[mt][nt][1];
            float* p1 = C + (size_t)(row + 8) * N + col;
            p1[0] = acc[mt][nt][2]; p1[1] = acc[mt][nt][3];
        }
    }
}

// ---------------- chunked parallel scan ----------------
__global__ void scan_pass1(const float* __restrict__ xp, const float* __restrict__ logd,
                           const float* __restrict__ bias, float* __restrict__ carry)
{
    int e = blockIdx.x * blockDim.x + threadIdx.x;
    int c = blockIdx.y;
    int b = blockIdx.z;
    float d  = sigmoidf_(logd[e]);
    float bb = bias[e];
    const float* xrow = xp + (size_t)(b * TLEN + c * CHUNK) * DINNER + e;
    float h = 0.f;
#pragma unroll 8
    for (int i = 0; i < CHUNK; i++)
        h = d * (xrow[(size_t)i * DINNER] + h) + bb;
    carry[((size_t)b * NCHUNK + c) * DINNER + e] = h;
}

__global__ void scan_pass2(const float* __restrict__ carry, const float* __restrict__ h0,
                           const float* __restrict__ logd, float* __restrict__ hin,
                           float* __restrict__ hfinal)
{
    int e = blockIdx.x * blockDim.x + threadIdx.x;
    int b = blockIdx.y;
    float d = sigmoidf_(logd[e]);
    float dc = 1.f;
    for (int i = 0; i < CHUNK; i++) dc *= d;   // d^CHUNK
    float h = h0[(size_t)b * DINNER + e];
#pragma unroll 1
    for (int c = 0; c < NCHUNK; c++) {
        size_t idx = ((size_t)b * NCHUNK + c) * DINNER + e;
        hin[idx] = h;
        h = dc * h + carry[idx];
    }
    hfinal[(size_t)b * DINNER + e] = h;
}

__global__ void scan_pass3(const float* __restrict__ xp, const float* __restrict__ hin,
                           const float* __restrict__ logd, const float* __restrict__ bias,
                           __half* __restrict__ ch)
{
    int e = blockIdx.x * blockDim.x + threadIdx.x;
    int c = blockIdx.y;
    int b = blockIdx.z;
    float d  = sigmoidf_(logd[e]);
    float bb = bias[e];
    float h = hin[((size_t)b * NCHUNK + c) * DINNER + e];
    const size_t base = (size_t)(b * TLEN + c * CHUNK) * DINNER + e;
#pragma unroll 4
    for (int i = 0; i < CHUNK; i++) {
        h = d * (xp[base + (size_t)i * DINNER] + h) + bb;
        float cell = h * h * sigmoidf_(h);       // h * silu(h)
        ch[base + (size_t)i * DINNER] = __float2half_rn(cell);
    }
}

// ---------------- launch ----------------
extern "C" void kernel_launch(void* const* d_in, const int* in_sizes, int n_in,
                              void* d_out, int out_size)
{
    const float* x    = (const float*)d_in[0];
    const float* h0   = (const float*)d_in[1];
    const float* Win  = (const float*)d_in[2];
    const float* Wout = (const float*)d_in[3];
    const float* logd = (const float*)d_in[4];
    const float* bias = (const float*)d_in[5];
    float* out    = (float*)d_out;
    float* hfinal = out + (size_t)MROWS * DIMX;

    void *xah, *xal, *wih, *wil, *woh, *wol, *xp, *ch, *carry, *hin;
    cudaGetSymbolAddress(&xah, g_xah);
    cudaGetSymbolAddress(&xal, g_xal);
    cudaGetSymbolAddress(&wih, g_wih);
    cudaGetSymbolAddress(&wil, g_wil);
    cudaGetSymbolAddress(&woh, g_woh);
    cudaGetSymbolAddress(&wol, g_wol);
    cudaGetSymbolAddress(&xp,  g_xp);
    cudaGetSymbolAddress(&ch,  g_ch);
    cudaGetSymbolAddress(&carry, g_carry);
    cudaGetSymbolAddress(&hin, g_hin);

    cudaFuncSetAttribute(gemm_s8_silu, cudaFuncAttributeMaxDynamicSharedMemorySize, G1_SMEM);
    cudaFuncSetAttribute(gemm_f16_2p,  cudaFuncAttributeMaxDynamicSharedMemorySize, G2_SMEM);

    // quantize / split operands
    quant_s8_kernel<<<2048, 256>>>((const float4*)x,   (uchar4*)xah, (uchar4*)xal, QX, MROWS * DIMX / 4);
    quant_s8_kernel<<<512,  256>>>((const float4*)Win, (uchar4*)wih, (uchar4*)wil, QW, DINNER * DIMX / 4);
    split_f16_kernel<<<512, 256>>>((const float4*)Wout, (uint2*)woh, (uint2*)wol, DIMX * DINNER / 4);

    // GEMM1: xp = silu(x @ W_in^T)   [16384 x 2048], int8 dual-word
    gemm_s8_silu<<<dim3(DINNER / BN, MROWS / BM), 256, G1_SMEM>>>(
        (const int8_t*)xah, (const int8_t*)xal,
        (const int8_t*)wih, (const int8_t*)wil,
        (float*)xp, MROWS, DINNER, DIMX);

    // chunked scan + gating (emits fp16 cell and fp32 h_final)
    scan_pass1<<<dim3(DINNER / 256, NCHUNK, BATCH), 256>>>((const float*)xp, logd, bias, (float*)carry);
    scan_pass2<<<dim3(DINNER / 256, BATCH), 256>>>((const float*)carry, h0, logd, (float*)hin, hfinal);
    scan_pass3<<<dim3(DINNER / 256, NCHUNK, BATCH), 256>>>((const float*)xp, (const float*)hin, logd, bias,
        (__half*)ch);

    // GEMM2: output = cell @ W_out^T   [16384 x 2048], fp16 2-product
    gemm_f16_2p<<<dim3(DIMX / BN, MROWS / BM), 256, G2_SMEM>>>(
        (const __half*)ch, (const __half*)woh, (const __half*)wol,
        out, MROWS, DIMX, DINNER);
}

// round 10
// speedup vs baseline: 2.4460x; 2.4460x over previous
#include <cuda_runtime.h>
#include <cuda_fp16.h>
#include <cstdint>
#include <cstddef>

// ---------------- problem dims ----------------
constexpr int DIMX   = 2048;
constexpr int DINNER = 2048;
constexpr int BATCH  = 4;
constexpr int TLEN   = 4096;
constexpr int MROWS  = BATCH * TLEN;     // 16384
constexpr int CHUNK  = 128;              // scan chunk length
constexpr int NCHUNK = TLEN / CHUNK;     // 32

// ---------------- GEMM tiling ----------------
constexpr int BM = 128, BN = 128, BK = 64;        // BK in fp16 elements
constexpr int TILE_B  = 128 * 128;                // 16384 B per smem tile (128 rows x 128B)
constexpr int STAGE_B = 3 * TILE_B;               // A, Bh, Bl = 49152
constexpr int NSTAGE  = 3;                        // triple buffer
constexpr int SMEM_TOT = NSTAGE * STAGE_B;        // 147456

// ---------------- device scratch (no allocations allowed) ----------------
__device__ __align__(256) __half g_xa[(size_t)MROWS * DIMX];
__device__ __align__(256) __half g_wih[(size_t)DINNER * DIMX];
__device__ __align__(256) __half g_wil[(size_t)DINNER * DIMX];
__device__ __align__(256) __half g_woh[(size_t)DIMX * DINNER];
__device__ __align__(256) __half g_wol[(size_t)DIMX * DINNER];
__device__ __align__(256) float  g_xp[(size_t)MROWS * DINNER];
__device__ __align__(256) __half g_ch[(size_t)MROWS * DINNER];
__device__ __align__(256) float  g_carry[(size_t)BATCH * NCHUNK * DINNER];
__device__ __align__(256) float  g_hin[(size_t)BATCH * NCHUNK * DINNER];

// ---------------- helpers ----------------
__device__ __forceinline__ float sigmoidf_(float x) { return 1.f / (1.f + __expf(-x)); }
__device__ __forceinline__ float siluf(float x)     { return x * sigmoidf_(x); }

__device__ __forceinline__ void cp16(uint32_t saddr, const void* gaddr) {
    asm volatile("cp.async.cg.shared.global [%0], [%1], 16;\n" :: "r"(saddr), "l"(gaddr));
}
__device__ __forceinline__ void ldm4(uint32_t (&d)[4], uint32_t saddr) {
    asm volatile("ldmatrix.sync.aligned.m8n8.x4.shared.b16 {%0,%1,%2,%3}, [%4];\n"
                 : "=r"(d[0]), "=r"(d[1]), "=r"(d[2]), "=r"(d[3]) : "r"(saddr));
}
__device__ __forceinline__ void mma_f16(float (&c)[4], const uint32_t (&a)[4], const uint32_t* b) {
    asm volatile("mma.sync.aligned.m16n8k16.row.col.f32.f16.f16.f32 "
                 "{%0,%1,%2,%3},{%4,%5,%6,%7},{%8,%9},{%0,%1,%2,%3};\n"
                 : "+f"(c[0]), "+f"(c[1]), "+f"(c[2]), "+f"(c[3])
                 : "r"(a[0]), "r"(a[1]), "r"(a[2]), "r"(a[3]), "r"(b[0]), "r"(b[1]));
}

// ---------------- fp32 -> fp16 cast (vectorized) ----------------
__global__ void cast_f16_kernel(const float4* __restrict__ src, uint2* __restrict__ dst, int n4)
{
    int i = blockIdx.x * blockDim.x + threadIdx.x;
    int stride = gridDim.x * blockDim.x;
    for (; i < n4; i += stride) {
        float4 v = src[i];
        __half hx = __float2half_rn(v.x), hy = __float2half_rn(v.y);
        __half hz = __float2half_rn(v.z), hw = __float2half_rn(v.w);
        uint2 H;
        H.x = ((uint32_t)__half_as_ushort(hy) << 16) | __half_as_ushort(hx);
        H.y = ((uint32_t)__half_as_ushort(hw) << 16) | __half_as_ushort(hz);
        dst[i] = H;
    }
}

// ---------------- fp32 -> fp16 hi/lo split (for weights) ----------------
__global__ void split_f16_kernel(const float4* __restrict__ src,
                                 uint2* __restrict__ hi, uint2* __restrict__ lo, int n4)
{
    int i = blockIdx.x * blockDim.x + threadIdx.x;
    int stride = gridDim.x * blockDim.x;
    for (; i < n4; i += stride) {
        float4 v = src[i];
        __half hx = __float2half_rn(v.x), hy = __float2half_rn(v.y);
        __half hz = __float2half_rn(v.z), hw = __float2half_rn(v.w);
        __half lx = __float2half_rn(v.x - __half2float(hx));
        __half ly = __float2half_rn(v.y - __half2float(hy));
        __half lz = __float2half_rn(v.z - __half2float(hz));
        __half lw = __float2half_rn(v.w - __half2float(hw));
        uint2 H, L;
        H.x = ((uint32_t)__half_as_ushort(hy) << 16) | __half_as_ushort(hx);
        H.y = ((uint32_t)__half_as_ushort(hw) << 16) | __half_as_ushort(hz);
        L.x = ((uint32_t)__half_as_ushort(ly) << 16) | __half_as_ushort(lx);
        L.y = ((uint32_t)__half_as_ushort(lw) << 16) | __half_as_ushort(lz);
        hi[i] = H; lo[i] = L;
    }
}

// ---------------- fp16 2-product GEMM: C = A * (Bh+Bl)^T  (fp32 acc) --------
// A[M,K] fp16 single, B[N,K] fp16 hi/lo planar. acc += A*Bh + A*Bl.
// smem: 128B rows, 16B chunks XOR-swizzled by (row&7). 3-stage cp.async pipe.
template <bool SILU>
__global__ void __launch_bounds__(256, 1)
gemm_f16_2p(const __half* __restrict__ A,
            const __half* __restrict__ Bh, const __half* __restrict__ Bl,
            float* __restrict__ C, int M, int N, int K)
{
    extern __shared__ char smem[];
    const int tid  = threadIdx.x;
    const int lane = tid & 31;
    const int wid  = tid >> 5;
    const int wm   = (wid >> 2) * 64;   // 2 warps in M
    const int wn   = (wid & 3) * 32;    // 4 warps in N
    const int bm   = blockIdx.y * BM;
    const int bn   = blockIdx.x * BN;
    const uint32_t sbase = (uint32_t)__cvta_generic_to_shared(smem);

    float acc[4][4][4];
#pragma unroll
    for (int i = 0; i < 4; i++)
#pragma unroll
        for (int j = 0; j < 4; j++)
#pragma unroll
            for (int q = 0; q < 4; q++) acc[i][j][q] = 0.f;

    const __half* gA   = A  + (size_t)bm * K;
    const __half* gB_h = Bh + (size_t)bn * K;
    const __half* gB_l = Bl + (size_t)bn * K;

    const int c_ld  = tid & 7;    // 16B chunk within 128B row
    const int r0_ld = tid >> 3;   // row 0..31 (+32 per iter)

    auto load_stage = [&](int s) {
        uint32_t st = sbase + (uint32_t)(s % NSTAGE) * STAGE_B;
        int k0 = s * BK;
#pragma unroll
        for (int it = 0; it < 4; it++) {
            int r = r0_ld + it * 32;
            uint32_t soff = (uint32_t)(r * 128 + ((c_ld ^ (r & 7)) << 4));
            size_t goff = (size_t)r * K + k0 + c_ld * 8;
            cp16(st + soff,              gA   + goff);
            cp16(st + TILE_B + soff,     gB_h + goff);
            cp16(st + 2 * TILE_B + soff, gB_l + goff);
        }
        asm volatile("cp.async.commit_group;" ::: "memory");
    };

    // prologue
    load_stage(0);
    load_stage(1);

    const int NK = K / BK;   // 32 stages
#pragma unroll 1
    for (int ks = 0; ks < NK; ks++) {
        if (ks + 2 < NK) {
            load_stage(ks + 2);   // buffer (ks+2)%3 was freed by end-of-iter sync of ks-1
        } else {
            asm volatile("cp.async.commit_group;" ::: "memory");
        }
        asm volatile("cp.async.wait_group 2;" ::: "memory");
        __syncthreads();

        uint32_t st = sbase + (uint32_t)(ks % NSTAGE) * STAGE_B;
        uint32_t sA = st;
        uint32_t sB[2] = { st + TILE_B, st + 2 * TILE_B };

#pragma unroll
        for (int kk = 0; kk < 4; kk++) {          // 4 x k16 per stage
            uint32_t a[4][4];
            {
                int ra  = wm + (lane & 15);
                int cha = kk * 2 + (lane >> 4);
#pragma unroll
                for (int mt = 0; mt < 4; mt++) {
                    int r = ra + mt * 16;
                    ldm4(a[mt], sA + (uint32_t)(r * 128 + ((cha ^ (r & 7)) << 4)));
                }
            }
            uint32_t b[2][4][2];
            {
                int rb  = wn + ((lane >> 4) << 3) + (lane & 7);
                int chb = kk * 2 + ((lane >> 3) & 1);
#pragma unroll
                for (int h = 0; h < 2; h++)
#pragma unroll
                    for (int p = 0; p < 2; p++) {
                        int r = rb + p * 16;
                        uint32_t t4[4];
                        ldm4(t4, sB[h] + (uint32_t)(r * 128 + ((chb ^ (r & 7)) << 4)));
                        b[h][2 * p    ][0] = t4[0]; b[h][2 * p    ][1] = t4[1];
                        b[h][2 * p + 1][0] = t4[2]; b[h][2 * p + 1][1] = t4[3];
                    }
            }
#pragma unroll
            for (int mt = 0; mt < 4; mt++)
#pragma unroll
                for (int nt = 0; nt < 4; nt++) {
                    mma_f16(acc[mt][nt], a[mt], b[0][nt]);  // A*Bh
                    mma_f16(acc[mt][nt], a[mt], b[1][nt]);  // A*Bl
                }
        }
        __syncthreads();
    }

    // epilogue
#pragma unroll
    for (int mt = 0; mt < 4; mt++) {
        int row = bm + wm + mt * 16 + (lane >> 2);
#pragma unroll
        for (int nt = 0; nt < 4; nt++) {
            int col = bn + wn + nt * 8 + (lane & 3) * 2;
            float v0 = acc[mt][nt][0], v1 = acc[mt][nt][1];
            float v2 = acc[mt][nt][2], v3 = acc[mt][nt][3];
            if (SILU) { v0 = siluf(v0); v1 = siluf(v1); v2 = siluf(v2); v3 = siluf(v3); }
            float* p0 = C + (size_t)row * N + col;
            p0[0] = v0; p0[1] = v1;
            float* p1 = C + (size_t)(row + 8) * N + col;
            p1[0] = v2; p1[1] = v3;
        }
    }
}

// ---------------- chunked parallel scan ----------------
// h_t = d*(x_t + h_{t-1}) + b  (linear). Over a chunk of C steps:
//   h_end = d^C * h_in + h_local(h_in = 0)

__global__ void scan_pass1(const float* __restrict__ xp, const float* __restrict__ logd,
                           const float* __restrict__ bias, float* __restrict__ carry)
{
    int e = blockIdx.x * blockDim.x + threadIdx.x;
    int c = blockIdx.y;
    int b = blockIdx.z;
    float d  = sigmoidf_(logd[e]);
    float bb = bias[e];
    const float* xrow = xp + (size_t)(b * TLEN + c * CHUNK) * DINNER + e;
    float h = 0.f;
#pragma unroll 8
    for (int i = 0; i < CHUNK; i++)
        h = d * (xrow[(size_t)i * DINNER] + h) + bb;
    carry[((size_t)b * NCHUNK + c) * DINNER + e] = h;
}

__global__ void scan_pass2(const float* __restrict__ carry, const float* __restrict__ h0,
                           const float* __restrict__ logd, float* __restrict__ hin,
                           float* __restrict__ hfinal)
{
    int e = blockIdx.x * blockDim.x + threadIdx.x;
    int b = blockIdx.y;
    float d = sigmoidf_(logd[e]);
    float dc = 1.f;
    for (int i = 0; i < CHUNK; i++) dc *= d;   // d^CHUNK
    float h = h0[(size_t)b * DINNER + e];
#pragma unroll 1
    for (int c = 0; c < NCHUNK; c++) {
        size_t idx = ((size_t)b * NCHUNK + c) * DINNER + e;
        hin[idx] = h;
        h = dc * h + carry[idx];
    }
    hfinal[(size_t)b * DINNER + e] = h;
}

__global__ void scan_pass3(const float* __restrict__ xp, const float* __restrict__ hin,
                           const float* __restrict__ logd, const float* __restrict__ bias,
                           __half* __restrict__ ch)
{
    int e = blockIdx.x * blockDim.x + threadIdx.x;
    int c = blockIdx.y;
    int b = blockIdx.z;
    float d  = sigmoidf_(logd[e]);
    float bb = bias[e];
    float h = hin[((size_t)b * NCHUNK + c) * DINNER + e];
    const size_t base = (size_t)(b * TLEN + c * CHUNK) * DINNER + e;
#pragma unroll 4
    for (int i = 0; i < CHUNK; i++) {
        h = d * (xp[base + (size_t)i * DINNER] + h) + bb;
        float cell = h * h * sigmoidf_(h);       // h * silu(h)
        ch[base + (size_t)i * DINNER] = __float2half_rn(cell);
    }
}

// ---------------- launch ----------------
extern "C" void kernel_launch(void* const* d_in, const int* in_sizes, int n_in,
                              void* d_out, int out_size)
{
    const float* x    = (const float*)d_in[0];
    const float* h0   = (const float*)d_in[1];
    const float* Win  = (const float*)d_in[2];
    const float* Wout = (const float*)d_in[3];
    const float* logd = (const float*)d_in[4];
    const float* bias = (const float*)d_in[5];
    float* out    = (float*)d_out;
    float* hfinal = out + (size_t)MROWS * DIMX;

    void *xa, *wih, *wil, *woh, *wol, *xp, *ch, *carry, *hin;
    cudaGetSymbolAddress(&xa,  g_xa);
    cudaGetSymbolAddress(&wih, g_wih);
    cudaGetSymbolAddress(&wil, g_wil);
    cudaGetSymbolAddress(&woh, g_woh);
    cudaGetSymbolAddress(&wol, g_wol);
    cudaGetSymbolAddress(&xp,  g_xp);
    cudaGetSymbolAddress(&ch,  g_ch);
    cudaGetSymbolAddress(&carry, g_carry);
    cudaGetSymbolAddress(&hin, g_hin);

    cudaFuncSetAttribute(gemm_f16_2p<true>,  cudaFuncAttributeMaxDynamicSharedMemorySize, SMEM_TOT);
    cudaFuncSetAttribute(gemm_f16_2p<false>, cudaFuncAttributeMaxDynamicSharedMemorySize, SMEM_TOT);

    // operand prep
    cast_f16_kernel<<<2048, 256>>>((const float4*)x, (uint2*)xa, MROWS * DIMX / 4);
    split_f16_kernel<<<512, 256>>>((const float4*)Win,  (uint2*)wih, (uint2*)wil, DINNER * DIMX / 4);
    split_f16_kernel<<<512, 256>>>((const float4*)Wout, (uint2*)woh, (uint2*)wol, DIMX * DINNER / 4);

    // GEMM1: xp = silu(x @ W_in^T)   [16384 x 2048], fp16 2-product
    gemm_f16_2p<true><<<dim3(DINNER / BN, MROWS / BM), 256, SMEM_TOT>>>(
        (const __half*)xa, (const __half*)wih, (const __half*)wil,
        (float*)xp, MROWS, DINNER, DIMX);

    // chunked scan + gating (emits fp16 cell and fp32 h_final)
    scan_pass1<<<dim3(DINNER / 256, NCHUNK, BATCH), 256>>>((const float*)xp, logd, bias, (float*)carry);
    scan_pass2<<<dim3(DINNER / 256, BATCH), 256>>>((const float*)carry, h0, logd, (float*)hin, hfinal);
    scan_pass3<<<dim3(DINNER / 256, NCHUNK, BATCH), 256>>>((const float*)xp, (const float*)hin, logd, bias,
        (__half*)ch);

    // GEMM2: output = cell @ W_out^T   [16384 x 2048], fp16 2-product
    gemm_f16_2p<false><<<dim3(DIMX / BN, MROWS / BM), 256, SMEM_TOT>>>(
        (const __half*)ch, (const __half*)woh, (const __half*)wol,
        out, MROWS, DIMX, DINNER);
}

// round 11
// speedup vs baseline: 2.8175x; 1.1519x over previous
#include <cuda_runtime.h>
#include <cuda_fp16.h>
#include <cstdint>
#include <cstddef>

// ---------------- problem dims ----------------
constexpr int DIMX   = 2048;
constexpr int DINNER = 2048;
constexpr int BATCH  = 4;
constexpr int TLEN   = 4096;
constexpr int MROWS  = BATCH * TLEN;     // 16384
constexpr int CHUNK  = 128;              // scan chunk length
constexpr int NCHUNK = TLEN / CHUNK;     // 32

// ---------------- GEMM tiling ----------------
constexpr int BM = 128, BN = 128, BK = 64;        // BK in fp16 elements
constexpr int TILE_B  = 128 * 128;                // 16384 B per smem tile (128 rows x 128B)
constexpr int STAGE_B = 3 * TILE_B;               // A, Bh, Bl = 49152
constexpr int NSTAGE  = 2;                        // double buffer -> 2 CTAs/SM
constexpr int SMEM_TOT = NSTAGE * STAGE_B;        // 98304

// ---------------- device scratch (no allocations allowed) ----------------
__device__ __align__(256) __half g_xa[(size_t)MROWS * DIMX];
__device__ __align__(256) __half g_wih[(size_t)DINNER * DIMX];
__device__ __align__(256) __half g_wil[(size_t)DINNER * DIMX];
__device__ __align__(256) __half g_woh[(size_t)DIMX * DINNER];
__device__ __align__(256) __half g_wol[(size_t)DIMX * DINNER];
__device__ __align__(256) float  g_xp[(size_t)MROWS * DINNER];
__device__ __align__(256) __half g_ch[(size_t)MROWS * DINNER];
__device__ __align__(256) float  g_carry[(size_t)BATCH * NCHUNK * DINNER];
__device__ __align__(256) float  g_hin[(size_t)BATCH * NCHUNK * DINNER];

// ---------------- helpers ----------------
__device__ __forceinline__ float sigmoidf_(float x) { return 1.f / (1.f + __expf(-x)); }
__device__ __forceinline__ float siluf(float x)     { return x * sigmoidf_(x); }

__device__ __forceinline__ void cp16(uint32_t saddr, const void* gaddr) {
    asm volatile("cp.async.cg.shared.global [%0], [%1], 16;\n" :: "r"(saddr), "l"(gaddr));
}
__device__ __forceinline__ void ldm4(uint32_t (&d)[4], uint32_t saddr) {
    asm volatile("ldmatrix.sync.aligned.m8n8.x4.shared.b16 {%0,%1,%2,%3}, [%4];\n"
                 : "=r"(d[0]), "=r"(d[1]), "=r"(d[2]), "=r"(d[3]) : "r"(saddr));
}
__device__ __forceinline__ void mma_f16(float (&c)[4], const uint32_t (&a)[4], const uint32_t* b) {
    asm volatile("mma.sync.aligned.m16n8k16.row.col.f32.f16.f16.f32 "
                 "{%0,%1,%2,%3},{%4,%5,%6,%7},{%8,%9},{%0,%1,%2,%3};\n"
                 : "+f"(c[0]), "+f"(c[1]), "+f"(c[2]), "+f"(c[3])
                 : "r"(a[0]), "r"(a[1]), "r"(a[2]), "r"(a[3]), "r"(b[0]), "r"(b[1]));
}

// ---------------- fp32 -> fp16 cast (vectorized) ----------------
__global__ void cast_f16_kernel(const float4* __restrict__ src, uint2* __restrict__ dst, int n4)
{
    int i = blockIdx.x * blockDim.x + threadIdx.x;
    int stride = gridDim.x * blockDim.x;
    for (; i < n4; i += stride) {
        float4 v = src[i];
        __half hx = __float2half_rn(v.x), hy = __float2half_rn(v.y);
        __half hz = __float2half_rn(v.z), hw = __float2half_rn(v.w);
        uint2 H;
        H.x = ((uint32_t)__half_as_ushort(hy) << 16) | __half_as_ushort(hx);
        H.y = ((uint32_t)__half_as_ushort(hw) << 16) | __half_as_ushort(hz);
        dst[i] = H;
    }
}

// ---------------- fp32 -> fp16 hi/lo split (for weights) ----------------
__global__ void split_f16_kernel(const float4* __restrict__ src,
                                 uint2* __restrict__ hi, uint2* __restrict__ lo, int n4)
{
    int i = blockIdx.x * blockDim.x + threadIdx.x;
    int stride = gridDim.x * blockDim.x;
    for (; i < n4; i += stride) {
        float4 v = src[i];
        __half hx = __float2half_rn(v.x), hy = __float2half_rn(v.y);
        __half hz = __float2half_rn(v.z), hw = __float2half_rn(v.w);
        __half lx = __float2half_rn(v.x - __half2float(hx));
        __half ly = __float2half_rn(v.y - __half2float(hy));
        __half lz = __float2half_rn(v.z - __half2float(hz));
        __half lw = __float2half_rn(v.w - __half2float(hw));
        uint2 H, L;
        H.x = ((uint32_t)__half_as_ushort(hy) << 16) | __half_as_ushort(hx);
        H.y = ((uint32_t)__half_as_ushort(hw) << 16) | __half_as_ushort(hz);
        L.x = ((uint32_t)__half_as_ushort(ly) << 16) | __half_as_ushort(lx);
        L.y = ((uint32_t)__half_as_ushort(lw) << 16) | __half_as_ushort(lz);
        hi[i] = H; lo[i] = L;
    }
}

// ---------------- fp16 2-product GEMM: C = A * (Bh+Bl)^T  (fp32 acc) --------
// A[M,K] fp16 single, B[N,K] fp16 hi/lo planar. acc += A*Bh + A*Bl.
// smem: 128B rows, 16B chunks XOR-swizzled by (row&7). Double-buffered
// cp.async pipe; 96KB smem + <=128 regs -> 2 CTAs/SM so barrier/ldmatrix
// bubbles of one CTA are covered by the other's HMMA issue.
template <bool SILU>
__global__ void __launch_bounds__(256, 2)
gemm_f16_2p(const __half* __restrict__ A,
            const __half* __restrict__ Bh, const __half* __restrict__ Bl,
            float* __restrict__ C, int M, int N, int K)
{
    extern __shared__ char smem[];
    const int tid  = threadIdx.x;
    const int lane = tid & 31;
    const int wid  = tid >> 5;
    const int wm   = (wid >> 2) * 64;   // 2 warps in M
    const int wn   = (wid & 3) * 32;    // 4 warps in N
    const int bm   = blockIdx.y * BM;
    const int bn   = blockIdx.x * BN;
    const uint32_t sbase = (uint32_t)__cvta_generic_to_shared(smem);

    float acc[4][4][4];
#pragma unroll
    for (int i = 0; i < 4; i++)
#pragma unroll
        for (int j = 0; j < 4; j++)
#pragma unroll
            for (int q = 0; q < 4; q++) acc[i][j][q] = 0.f;

    const __half* gA   = A  + (size_t)bm * K;
    const __half* gB_h = Bh + (size_t)bn * K;
    const __half* gB_l = Bl + (size_t)bn * K;

    const int c_ld  = tid & 7;    // 16B chunk within 128B row
    const int r0_ld = tid >> 3;   // row 0..31 (+32 per iter)

    auto load_stage = [&](int s) {
        uint32_t st = sbase + (uint32_t)(s & 1) * STAGE_B;
        int k0 = s * BK;
#pragma unroll
        for (int it = 0; it < 4; it++) {
            int r = r0_ld + it * 32;
            uint32_t soff = (uint32_t)(r * 128 + ((c_ld ^ (r & 7)) << 4));
            size_t goff = (size_t)r * K + k0 + c_ld * 8;
            cp16(st + soff,              gA   + goff);
            cp16(st + TILE_B + soff,     gB_h + goff);
            cp16(st + 2 * TILE_B + soff, gB_l + goff);
        }
        asm volatile("cp.async.commit_group;" ::: "memory");
    };

    // prologue
    load_stage(0);

    const int NK = K / BK;   // 32 stages
#pragma unroll 1
    for (int ks = 0; ks < NK; ks++) {
        if (ks + 1 < NK) {
            load_stage(ks + 1);   // writes buffer !cur (freed by end-of-iter sync of ks-1)
        } else {
            asm volatile("cp.async.commit_group;" ::: "memory");
        }
        asm volatile("cp.async.wait_group 1;" ::: "memory");
        __syncthreads();

        uint32_t st = sbase + (uint32_t)(ks & 1) * STAGE_B;
        uint32_t sA = st;
        uint32_t sB[2] = { st + TILE_B, st + 2 * TILE_B };

#pragma unroll
        for (int kk = 0; kk < 4; kk++) {          // 4 x k16 per stage
            uint32_t a[4][4];
            {
                int ra  = wm + (lane & 15);
                int cha = kk * 2 + (lane >> 4);
#pragma unroll
                for (int mt = 0; mt < 4; mt++) {
                    int r = ra + mt * 16;
                    ldm4(a[mt], sA + (uint32_t)(r * 128 + ((cha ^ (r & 7)) << 4)));
                }
            }
            // process B halves sequentially to keep register pressure low
#pragma unroll
            for (int h = 0; h < 2; h++) {
                uint32_t b[4][2];
                {
                    int rb  = wn + ((lane >> 4) << 3) + (lane & 7);
                    int chb = kk * 2 + ((lane >> 3) & 1);
#pragma unroll
                    for (int p = 0; p < 2; p++) {
                        int r = rb + p * 16;
                        uint32_t t4[4];
                        ldm4(t4, sB[h] + (uint32_t)(r * 128 + ((chb ^ (r & 7)) << 4)));
                        b[2 * p    ][0] = t4[0]; b[2 * p    ][1] = t4[1];
                        b[2 * p + 1][0] = t4[2]; b[2 * p + 1][1] = t4[3];
                    }
                }
#pragma unroll
                for (int mt = 0; mt < 4; mt++)
#pragma unroll
                    for (int nt = 0; nt < 4; nt++)
                        mma_f16(acc[mt][nt], a[mt], b[nt]);
            }
        }
        __syncthreads();
    }

    // epilogue
#pragma unroll
    for (int mt = 0; mt < 4; mt++) {
        int row = bm + wm + mt * 16 + (lane >> 2);
#pragma unroll
        for (int nt = 0; nt < 4; nt++) {
            int col = bn + wn + nt * 8 + (lane & 3) * 2;
            float v0 = acc[mt][nt][0], v1 = acc[mt][nt][1];
            float v2 = acc[mt][nt][2], v3 = acc[mt][nt][3];
            if (SILU) { v0 = siluf(v0); v1 = siluf(v1); v2 = siluf(v2); v3 = siluf(v3); }
            float* p0 = C + (size_t)row * N + col;
            p0[0] = v0; p0[1] = v1;
            float* p1 = C + (size_t)(row + 8) * N + col;
            p1[0] = v2; p1[1] = v3;
        }
    }
}

// ---------------- chunked parallel scan ----------------
// h_t = d*(x_t + h_{t-1}) + b  (linear). Over a chunk of C steps:
//   h_end = d^C * h_in + h_local(h_in = 0)

__global__ void scan_pass1(const float* __restrict__ xp, const float* __restrict__ logd,
                           const float* __restrict__ bias, float* __restrict__ carry)
{
    int e = blockIdx.x * blockDim.x + threadIdx.x;
    int c = blockIdx.y;
    int b = blockIdx.z;
    float d  = sigmoidf_(logd[e]);
    float bb = bias[e];
    const float* xrow = xp + (size_t)(b * TLEN + c * CHUNK) * DINNER + e;
    float h = 0.f;
#pragma unroll 8
    for (int i = 0; i < CHUNK; i++)
        h = d * (xrow[(size_t)i * DINNER] + h) + bb;
    carry[((size_t)b * NCHUNK + c) * DINNER + e] = h;
}

__global__ void scan_pass2(const float* __restrict__ carry, const float* __restrict__ h0,
                           const float* __restrict__ logd, float* __restrict__ hin,
                           float* __restrict__ hfinal)
{
    int e = blockIdx.x * blockDim.x + threadIdx.x;
    int b = blockIdx.y;
    float d = sigmoidf_(logd[e]);
    float dc = 1.f;
    for (int i = 0; i < CHUNK; i++) dc *= d;   // d^CHUNK
    float h = h0[(size_t)b * DINNER + e];
#pragma unroll 1
    for (int c = 0; c < NCHUNK; c++) {
        size_t idx = ((size_t)b * NCHUNK + c) * DINNER + e;
        hin[idx] = h;
        h = dc * h + carry[idx];
    }
    hfinal[(size_t)b * DINNER + e] = h;
}

__global__ void scan_pass3(const float* __restrict__ xp, const float* __restrict__ hin,
                           const float* __restrict__ logd, const float* __restrict__ bias,
                           __half* __restrict__ ch)
{
    int e = blockIdx.x * blockDim.x + threadIdx.x;
    int c = blockIdx.y;
    int b = blockIdx.z;
    float d  = sigmoidf_(logd[e]);
    float bb = bias[e];
    float h = hin[((size_t)b * NCHUNK + c) * DINNER + e];
    const size_t base = (size_t)(b * TLEN + c * CHUNK) * DINNER + e;
#pragma unroll 4
    for (int i = 0; i < CHUNK; i++) {
        h = d * (xp[base + (size_t)i * DINNER] + h) + bb;
        float cell = h * h * sigmoidf_(h);       // h * silu(h)
        ch[base + (size_t)i * DINNER] = __float2half_rn(cell);
    }
}

// ---------------- launch ----------------
extern "C" void kernel_launch(void* const* d_in, const int* in_sizes, int n_in,
                              void* d_out, int out_size)
{
    const float* x    = (const float*)d_in[0];
    const float* h0   = (const float*)d_in[1];
    const float* Win  = (const float*)d_in[2];
    const float* Wout = (const float*)d_in[3];
    const float* logd = (const float*)d_in[4];
    const float* bias = (const float*)d_in[5];
    float* out    = (float*)d_out;
    float* hfinal = out + (size_t)MROWS * DIMX;

    void *xa, *wih, *wil, *woh, *wol, *xp, *ch, *carry, *hin;
    cudaGetSymbolAddress(&xa,  g_xa);
    cudaGetSymbolAddress(&wih, g_wih);
    cudaGetSymbolAddress(&wil, g_wil);
    cudaGetSymbolAddress(&woh, g_woh);
    cudaGetSymbolAddress(&wol, g_wol);
    cudaGetSymbolAddress(&xp,  g_xp);
    cudaGetSymbolAddress(&ch,  g_ch);
    cudaGetSymbolAddress(&carry, g_carry);
    cudaGetSymbolAddress(&hin, g_hin);

    cudaFuncSetAttribute(gemm_f16_2p<true>,  cudaFuncAttributeMaxDynamicSharedMemorySize, SMEM_TOT);
    cudaFuncSetAttribute(gemm_f16_2p<false>, cudaFuncAttributeMaxDynamicSharedMemorySize, SMEM_TOT);

    // operand prep
    cast_f16_kernel<<<2048, 256>>>((const float4*)x, (uint2*)xa, MROWS * DIMX / 4);
    split_f16_kernel<<<512, 256>>>((const float4*)Win,  (uint2*)wih, (uint2*)wil, DINNER * DIMX / 4);
    split_f16_kernel<<<512, 256>>>((const float4*)Wout, (uint2*)woh, (uint2*)wol, DIMX * DINNER / 4);

    // GEMM1: xp = silu(x @ W_in^T)   [16384 x 2048], fp16 2-product
    gemm_f16_2p<true><<<dim3(DINNER / BN, MROWS / BM), 256, SMEM_TOT>>>(
        (const __half*)xa, (const __half*)wih, (const __half*)wil,
        (float*)xp, MROWS, DINNER, DIMX);

    // chunked scan + gating (emits fp16 cell and fp32 h_final)
    scan_pass1<<<dim3(DINNER / 256, NCHUNK, BATCH), 256>>>((const float*)xp, logd, bias, (float*)carry);
    scan_pass2<<<dim3(DINNER / 256, BATCH), 256>>>((const float*)carry, h0, logd, (float*)hin, hfinal);
    scan_pass3<<<dim3(DINNER / 256, NCHUNK, BATCH), 256>>>((const float*)xp, (const float*)hin, logd, bias,
        (__half*)ch);

    // GEMM2: output = cell @ W_out^T   [16384 x 2048], fp16 2-product
    gemm_f16_2p<false><<<dim3(DIMX / BN, MROWS / BM), 256, SMEM_TOT>>>(
        (const __half*)ch, (const __half*)woh, (const __half*)wol,
        out, MROWS, DIMX, DINNER);
}

// round 13
// speedup vs baseline: 3.4963x; 1.2409x over previous
#include <cuda_runtime.h>
#include <cuda_fp16.h>
#include <cstdint>
#include <cstddef>

// ---------------- problem dims ----------------
constexpr int DIMX   = 2048;
constexpr int DINNER = 2048;
constexpr int BATCH  = 4;
constexpr int TLEN   = 4096;
constexpr int MROWS  = BATCH * TLEN;     // 16384
constexpr int CHUNK  = 128;              // scan chunk length
constexpr int NCHUNK = TLEN / CHUNK;     // 32

// ---------------- GEMM tiling ----------------
constexpr int BM = 128, BN = 128, BK = 64;        // BK in fp16 elements
constexpr int TILE_B  = 128 * 128;                // 16384 B per smem tile (128 rows x 128B)

// ---------------- device scratch (no allocations allowed) ----------------
__device__ __align__(256) __half g_xa[(size_t)MROWS * DIMX];
__device__ __align__(256) __half g_wih[(size_t)DINNER * DIMX];
__device__ __align__(256) __half g_wil[(size_t)DINNER * DIMX];
__device__ __align__(256) __half g_woh[(size_t)DIMX * DINNER];
__device__ __align__(256) float  g_xp[(size_t)MROWS * DINNER];
__device__ __align__(256) __half g_ch[(size_t)MROWS * DINNER];
__device__ __align__(256) float  g_carry[(size_t)BATCH * NCHUNK * DINNER];
__device__ __align__(256) float  g_hin[(size_t)BATCH * NCHUNK * DINNER];

// ---------------- helpers ----------------
__device__ __forceinline__ float sigmoidf_(float x) { return 1.f / (1.f + __expf(-x)); }
__device__ __forceinline__ float siluf(float x)     { return x * sigmoidf_(x); }

__device__ __forceinline__ void cp16(uint32_t saddr, const void* gaddr) {
    asm volatile("cp.async.cg.shared.global [%0], [%1], 16;\n" :: "r"(saddr), "l"(gaddr));
}
__device__ __forceinline__ void ldm4(uint32_t (&d)[4], uint32_t saddr) {
    asm volatile("ldmatrix.sync.aligned.m8n8.x4.shared.b16 {%0,%1,%2,%3}, [%4];\n"
                 : "=r"(d[0]), "=r"(d[1]), "=r"(d[2]), "=r"(d[3]) : "r"(saddr));
}
__device__ __forceinline__ void mma_f16(float (&c)[4], const uint32_t (&a)[4], const uint32_t* b) {
    asm volatile("mma.sync.aligned.m16n8k16.row.col.f32.f16.f16.f32 "
                 "{%0,%1,%2,%3},{%4,%5,%6,%7},{%8,%9},{%0,%1,%2,%3};\n"
                 : "+f"(c[0]), "+f"(c[1]), "+f"(c[2]), "+f"(c[3])
                 : "r"(a[0]), "r"(a[1]), "r"(a[2]), "r"(a[3]), "r"(b[0]), "r"(b[1]));
}

// ---------------- fp32 -> fp16 cast (vectorized) ----------------
__global__ void cast_f16_kernel(const float4* __restrict__ src, uint2* __restrict__ dst, int n4)
{
    int i = blockIdx.x * blockDim.x + threadIdx.x;
    int stride = gridDim.x * blockDim.x;
    for (; i < n4; i += stride) {
        float4 v = src[i];
        __half hx = __float2half_rn(v.x), hy = __float2half_rn(v.y);
        __half hz = __float2half_rn(v.z), hw = __float2half_rn(v.w);
        uint2 H;
        H.x = ((uint32_t)__half_as_ushort(hy) << 16) | __half_as_ushort(hx);
        H.y = ((uint32_t)__half_as_ushort(hw) << 16) | __half_as_ushort(hz);
        dst[i] = H;
    }
}

// ---------------- fp32 -> fp16 hi/lo split (for W_in) ----------------
__global__ void split_f16_kernel(const float4* __restrict__ src,
                                 uint2* __restrict__ hi, uint2* __restrict__ lo, int n4)
{
    int i = blockIdx.x * blockDim.x + threadIdx.x;
    int stride = gridDim.x * blockDim.x;
    for (; i < n4; i += stride) {
        float4 v = src[i];
        __half hx = __float2half_rn(v.x), hy = __float2half_rn(v.y);
        __half hz = __float2half_rn(v.z), hw = __float2half_rn(v.w);
        __half lx = __float2half_rn(v.x - __half2float(hx));
        __half ly = __float2half_rn(v.y - __half2float(hy));
        __half lz = __float2half_rn(v.z - __half2float(hz));
        __half lw = __float2half_rn(v.w - __half2float(hw));
        uint2 H, L;
        H.x = ((uint32_t)__half_as_ushort(hy) << 16) | __half_as_ushort(hx);
        H.y = ((uint32_t)__half_as_ushort(hw) << 16) | __half_as_ushort(hz);
        L.x = ((uint32_t)__half_as_ushort(ly) << 16) | __half_as_ushort(lx);
        L.y = ((uint32_t)__half_as_ushort(lw) << 16) | __half_as_ushort(lz);
        hi[i] = H; lo[i] = L;
    }
}

// ---------------- fp16 GEMM: C = A * (sum of NB B planes)^T  (fp32 acc) -----
// A[M,K] fp16 single; B planes (hi[,lo]) fp16 planar. acc += A*B0 [+ A*B1].
// smem: 128B rows, 16B chunks XOR-swizzled by (row&7). Double-buffered
// cp.async pipe; <=128 regs + smem sized for 2 CTAs/SM so one CTA's
// barrier/ldmatrix bubbles are covered by the other's HMMA issue.
template <bool SILU, int NB>
__global__ void __launch_bounds__(256, 2)
gemm_f16(const __half* __restrict__ A,
         const __half* __restrict__ B0, const __half* __restrict__ B1,
         float* __restrict__ C, int M, int N, int K)
{
    constexpr int NTILE   = 1 + NB;              // tiles per stage (A + B planes)
    constexpr int STAGE_B = NTILE * TILE_B;
    extern __shared__ char smem[];
    const int tid  = threadIdx.x;
    const int lane = tid & 31;
    const int wid  = tid >> 5;
    const int wm   = (wid >> 2) * 64;   // 2 warps in M
    const int wn   = (wid & 3) * 32;    // 4 warps in N
    const int bm   = blockIdx.y * BM;
    const int bn   = blockIdx.x * BN;
    const uint32_t sbase = (uint32_t)__cvta_generic_to_shared(smem);

    float acc[4][4][4];
#pragma unroll
    for (int i = 0; i < 4; i++)
#pragma unroll
        for (int j = 0; j < 4; j++)
#pragma unroll
            for (int q = 0; q < 4; q++) acc[i][j][q] = 0.f;

    const __half* gA  = A  + (size_t)bm * K;
    const __half* gB0 = B0 + (size_t)bn * K;
    const __half* gB1 = (NB == 2) ? (B1 + (size_t)bn * K) : nullptr;

    const int c_ld  = tid & 7;    // 16B chunk within 128B row
    const int r0_ld = tid >> 3;   // row 0..31 (+32 per iter)

    auto load_stage = [&](int s) {
        uint32_t st = sbase + (uint32_t)(s & 1) * STAGE_B;
        int k0 = s * BK;
#pragma unroll
        for (int it = 0; it < 4; it++) {
            int r = r0_ld + it * 32;
            uint32_t soff = (uint32_t)(r * 128 + ((c_ld ^ (r & 7)) << 4));
            size_t goff = (size_t)r * K + k0 + c_ld * 8;
            cp16(st + soff,          gA  + goff);
            cp16(st + TILE_B + soff, gB0 + goff);
            if (NB == 2)
                cp16(st + 2 * TILE_B + soff, gB1 + goff);
        }
        asm volatile("cp.async.commit_group;" ::: "memory");
    };

    // prologue
    load_stage(0);

    const int NK = K / BK;   // 32 stages
#pragma unroll 1
    for (int ks = 0; ks < NK; ks++) {
        if (ks + 1 < NK) {
            load_stage(ks + 1);   // writes buffer !cur (freed by end-of-iter sync of ks-1)
        } else {
            asm volatile("cp.async.commit_group;" ::: "memory");
        }
        asm volatile("cp.async.wait_group 1;" ::: "memory");
        __syncthreads();

        uint32_t st = sbase + (uint32_t)(ks & 1) * STAGE_B;
        uint32_t sA = st;

#pragma unroll
        for (int kk = 0; kk < 4; kk++) {          // 4 x k16 per stage
            uint32_t a[4][4];
            {
                int ra  = wm + (lane & 15);
                int cha = kk * 2 + (lane >> 4);
#pragma unroll
                for (int mt = 0; mt < 4; mt++) {
                    int r = ra + mt * 16;
                    ldm4(a[mt], sA + (uint32_t)(r * 128 + ((cha ^ (r & 7)) << 4)));
                }
            }
            // process B planes sequentially (keeps register pressure <=128)
#pragma unroll
            for (int h = 0; h < NB; h++) {
                uint32_t sB = st + (uint32_t)(1 + h) * TILE_B;
                uint32_t b[4][2];
                {
                    int rb  = wn + ((lane >> 4) << 3) + (lane & 7);
                    int chb = kk * 2 + ((lane >> 3) & 1);
#pragma unroll
                    for (int p = 0; p < 2; p++) {
                        int r = rb + p * 16;
                        uint32_t t4[4];
                        ldm4(t4, sB + (uint32_t)(r * 128 + ((chb ^ (r & 7)) << 4)));
                        b[2 * p    ][0] = t4[0]; b[2 * p    ][1] = t4[1];
                        b[2 * p + 1][0] = t4[2]; b[2 * p + 1][1] = t4[3];
                    }
                }
#pragma unroll
                for (int mt = 0; mt < 4; mt++)
#pragma unroll
                    for (int nt = 0; nt < 4; nt++)
                        mma_f16(acc[mt][nt], a[mt], b[nt]);
            }
        }
        __syncthreads();
    }

    // epilogue
#pragma unroll
    for (int mt = 0; mt < 4; mt++) {
        int row = bm + wm + mt * 16 + (lane >> 2);
#pragma unroll
        for (int nt = 0; nt < 4; nt++) {
            int col = bn + wn + nt * 8 + (lane & 3) * 2;
            float v0 = acc[mt][nt][0], v1 = acc[mt][nt][1];
            float v2 = acc[mt][nt][2], v3 = acc[mt][nt][3];
            if (SILU) { v0 = siluf(v0); v1 = siluf(v1); v2 = siluf(v2); v3 = siluf(v3); }
            float* p0 = C + (size_t)row * N + col;
            p0[0] = v0; p0[1] = v1;
            float* p1 = C + (size_t)(row + 8) * N + col;
            p1[0] = v2; p1[1] = v3;
        }
    }
}

// ---------------- chunked parallel scan ----------------
// h_t = d*(x_t + h_{t-1}) + b  (linear). Over a chunk of C steps:
//   h_end = d^C * h_in + h_local(h_in = 0)

__global__ void scan_pass1(const float* __restrict__ xp, const float* __restrict__ logd,
                           const float* __restrict__ bias, float* __restrict__ carry)
{
    int e = blockIdx.x * blockDim.x + threadIdx.x;
    int c = blockIdx.y;
    int b = blockIdx.z;
    float d  = sigmoidf_(logd[e]);
    float bb = bias[e];
    const float* xrow = xp + (size_t)(b * TLEN + c * CHUNK) * DINNER + e;
    float h = 0.f;
#pragma unroll 8
    for (int i = 0; i < CHUNK; i++)
        h = d * (xrow[(size_t)i * DINNER] + h) + bb;
    carry[((size_t)b * NCHUNK + c) * DINNER + e] = h;
}

__global__ void scan_pass2(const float* __restrict__ carry, const float* __restrict__ h0,
                           const float* __restrict__ logd, float* __restrict__ hin,
                           float* __restrict__ hfinal)
{
    int e = blockIdx.x * blockDim.x + threadIdx.x;
    int b = blockIdx.y;
    float d = sigmoidf_(logd[e]);
    float dc = 1.f;
    for (int i = 0; i < CHUNK; i++) dc *= d;   // d^CHUNK
    float h = h0[(size_t)b * DINNER + e];
#pragma unroll 1
    for (int c = 0; c < NCHUNK; c++) {
        size_t idx = ((size_t)b * NCHUNK + c) * DINNER + e;
        hin[idx] = h;
        h = dc * h + carry[idx];
    }
    hfinal[(size_t)b * DINNER + e] = h;
}

__global__ void scan_pass3(const float* __restrict__ xp, const float* __restrict__ hin,
                           const float* __restrict__ logd, const float* __restrict__ bias,
                           __half* __restrict__ ch)
{
    int e = blockIdx.x * blockDim.x + threadIdx.x;
    int c = blockIdx.y;
    int b = blockIdx.z;
    float d  = sigmoidf_(logd[e]);
    float bb = bias[e];
    float h = hin[((size_t)b * NCHUNK + c) * DINNER + e];
    const size_t base = (size_t)(b * TLEN + c * CHUNK) * DINNER + e;
#pragma unroll 4
    for (int i = 0; i < CHUNK; i++) {
        h = d * (xp[base + (size_t)i * DINNER] + h) + bb;
        float cell = h * h * sigmoidf_(h);       // h * silu(h)
        ch[base + (size_t)i * DINNER] = __float2half_rn(cell);
    }
}

// ---------------- launch ----------------
extern "C" void kernel_launch(void* const* d_in, const int* in_sizes, int n_in,
                              void* d_out, int out_size)
{
    const float* x    = (const float*)d_in[0];
    const float* h0   = (const float*)d_in[1];
    const float* Win  = (const float*)d_in[2];
    const float* Wout = (const float*)d_in[3];
    const float* logd = (const float*)d_in[4];
    const float* bias = (const float*)d_in[5];
    float* out    = (float*)d_out;
    float* hfinal = out + (size_t)MROWS * DIMX;

    void *xa, *wih, *wil, *woh, *xp, *ch, *carry, *hin;
    cudaGetSymbolAddress(&xa,  g_xa);
    cudaGetSymbolAddress(&wih, g_wih);
    cudaGetSymbolAddress(&wil, g_wil);
    cudaGetSymbolAddress(&woh, g_woh);
    cudaGetSymbolAddress(&xp,  g_xp);
    cudaGetSymbolAddress(&ch,  g_ch);
    cudaGetSymbolAddress(&carry, g_carry);
    cudaGetSymbolAddress(&hin, g_hin);

    constexpr int SMEM_G1 = 2 * 3 * TILE_B;   // 98304 (A,Bh,Bl double-buffered)
    constexpr int SMEM_G2 = 2 * 2 * TILE_B;   // 65536 (A,B double-buffered)
    cudaFuncSetAttribute(gemm_f16<true, 2>,  cudaFuncAttributeMaxDynamicSharedMemorySize, SMEM_G1);
    cudaFuncSetAttribute(gemm_f16<false, 1>, cudaFuncAttributeMaxDynamicSharedMemorySize, SMEM_G2);

    // operand prep
    cast_f16_kernel<<<2048, 256>>>((const float4*)x, (uint2*)xa, MROWS * DIMX / 4);
    split_f16_kernel<<<512, 256>>>((const float4*)Win, (uint2*)wih, (uint2*)wil, DINNER * DIMX / 4);
    cast_f16_kernel<<<512, 256>>>((const float4*)Wout, (uint2*)woh, DIMX * DINNER / 4);

    // GEMM1: xp = silu(x @ W_in^T)  [16384 x 2048], fp16 2-product (W_in hi/lo)
    gemm_f16<true, 2><<<dim3(DINNER / BN, MROWS / BM), 256, SMEM_G1>>>(
        (const __half*)xa, (const __half*)wih, (const __half*)wil,
        (float*)xp, MROWS, DINNER, DIMX);

    // chunked scan + gating (emits fp16 cell and fp32 h_final)
    scan_pass1<<<dim3(DINNER / 256, NCHUNK, BATCH), 256>>>((const float*)xp, logd, bias, (float*)carry);
    scan_pass2<<<dim3(DINNER / 256, BATCH), 256>>>((const float*)carry, h0, logd, (float*)hin, hfinal);
    scan_pass3<<<dim3(DINNER / 256, NCHUNK, BATCH), 256>>>((const float*)xp, (const float*)hin, logd, bias,
        (__half*)ch);

    // GEMM2: output = cell @ W_out^T  [16384 x 2048], fp16 single product
    gemm_f16<false, 1><<<dim3(DIMX / BN, MROWS / BM), 256, SMEM_G2>>>(
        (const __half*)ch, (const __half*)woh, nullptr,
        out, MROWS, DIMX, DINNER);
}